// round 4
// baseline (speedup 1.0000x reference)
#include <cuda_runtime.h>
#include <cuda_bf16.h>

// Problem constants (fixed shapes)
#define S_NUM   16
#define T_MAX   11
#define ROWS    64
#define HID     768
#define SEQ     512

#define BERT_ELEMS   (S_NUM * SEQ * HID)        // 6291456
#define MTL_OFF      BERT_ELEMS
#define MTL_ELEMS    (S_NUM * HID)              // 12288
#define PROBS_OFF    (MTL_OFF + MTL_ELEMS)
#define PROBS_ELEMS  (S_NUM * T_MAX)            // 176

#define E4_PER_SLICE (SEQ * (HID / 4))          // 512*192 = 98304 float4 per slice
#define TOTAL_E4     (S_NUM * E4_PER_SLICE)     // 1572864

// Scratch (no device mallocs allowed)
__device__ int   g_off[S_NUM];
__device__ int   g_ns[S_NUM];
__device__ float g_w[ROWS];

// ---------------------------------------------------------------------------
// Kernel A: offsets, logits, softmax, per-row weights, mtl segment-sum, probs
// One block, 256 threads.
// ---------------------------------------------------------------------------
__global__ void __launch_bounds__(256, 1)
small_kernel(const float* __restrict__ hist,     // [ROWS, HID]
             const float* __restrict__ mtl,      // [ROWS, HID]
             const float* __restrict__ W,        // [1, HID]
             const float* __restrict__ b,        // [1]
             const int*   __restrict__ slice_mask,
             float*       __restrict__ out)
{
    __shared__ float s_logits[S_NUM * T_MAX];
    __shared__ int   s_valid[S_NUM * T_MAX];
    __shared__ int   s_off[S_NUM];
    __shared__ int   s_ns[S_NUM];
    __shared__ float s_probs[S_NUM * T_MAX];
    __shared__ float s_w[ROWS];

    const int tid  = threadIdx.x;
    const int lane = tid & 31;
    const int wid  = tid >> 5;

    // 1) serial cumsum of slice sizes (16 elems, thread 0)
    if (tid == 0) {
        int off = 0;
        for (int s = 0; s < S_NUM; s++) {
            int n = slice_mask[s];
            s_off[s] = off;
            s_ns[s]  = n;
            g_off[s] = off;
            g_ns[s]  = n;
            off += n;
        }
    }
    __syncthreads();

    // 2) logits: warp per (s,t) pair, 8 warps loop over 176 pairs
    const float bias = b[0];
    for (int p = wid; p < S_NUM * T_MAX; p += 8) {
        int s = p / T_MAX;
        int t = p % T_MAX;
        int n = s_ns[s];
        int pad = T_MAX - n;
        if (t >= pad) {
            int row = s_off[s] + t - pad;
            float acc = 0.f;
            const float* hrow = hist + (long)row * HID;
            for (int k = lane; k < HID; k += 32)
                acc += hrow[k] * W[k];
            // warp reduce
            #pragma unroll
            for (int d = 16; d > 0; d >>= 1)
                acc += __shfl_xor_sync(0xffffffffu, acc, d);
            if (lane == 0) { s_logits[p] = acc + bias; s_valid[p] = 1; }
        } else {
            if (lane == 0) { s_logits[p] = 0.f; s_valid[p] = 0; }
        }
    }
    __syncthreads();

    // 3) softmax per slice + per-row weights (16 threads)
    if (tid < S_NUM) {
        int s = tid;
        int n = s_ns[s];
        int pad = T_MAX - n;
        float denom = 0.f;
        float e[T_MAX];
        for (int t = 0; t < T_MAX; t++) {
            float v = s_valid[s * T_MAX + t] ? expf(s_logits[s * T_MAX + t]) : 0.f;
            e[t] = v;
            denom += v;
        }
        float inv = 1.f / denom;
        for (int t = 0; t < T_MAX; t++)
            s_probs[s * T_MAX + t] = e[t] * inv;
        // weight for each row in this slice: row (off+j) -> probs[s, pad+j]
        for (int j = 0; j < n; j++) {
            float wv = s_probs[s * T_MAX + pad + j];
            s_w[s_off[s] + j] = wv;
            g_w[s_off[s] + j] = wv;
        }
    }
    __syncthreads();

    // 4) write probs output
    for (int p = tid; p < S_NUM * T_MAX; p += 256)
        out[PROBS_OFF + p] = s_probs[p];

    // 5) mtl segment-sum: 16*768 outputs
    for (int e = tid; e < S_NUM * HID; e += 256) {
        int s = e / HID;
        int h = e - s * HID;
        int off = s_off[s];
        int n   = s_ns[s];
        float acc = 0.f;
        for (int j = 0; j < n; j++)
            acc += mtl[(long)(off + j) * HID + h] * s_w[off + j];
        out[MTL_OFF + e] = acc;
    }
}

// ---------------------------------------------------------------------------
// Kernel B: weighted segment-sum of bert_representation, float4 vectorized.
// out[s, :, :] = sum_j w[off[s]+j] * bert[off[s]+j, :, :]
// ---------------------------------------------------------------------------
__global__ void __launch_bounds__(256)
bert_kernel(const float4* __restrict__ bert, float4* __restrict__ out)
{
    int i = blockIdx.x * blockDim.x + threadIdx.x;
    if (i >= TOTAL_E4) return;
    int s = i / E4_PER_SLICE;
    int e = i - s * E4_PER_SLICE;

    int off = g_off[s];
    int n   = g_ns[s];

    float4 acc = make_float4(0.f, 0.f, 0.f, 0.f);
    for (int j = 0; j < n; j++) {
        float w = g_w[off + j];
        float4 v = bert[(long)(off + j) * E4_PER_SLICE + e];
        acc.x += w * v.x;
        acc.y += w * v.y;
        acc.z += w * v.z;
        acc.w += w * v.w;
    }
    out[i] = acc;
}

extern "C" void kernel_launch(void* const* d_in, const int* in_sizes, int n_in,
                              void* d_out, int out_size)
{
    const float* bert  = (const float*)d_in[0];   // [64, 512, 768]
    const float* hist  = (const float*)d_in[1];   // [64, 768]
    const float* mtl   = (const float*)d_in[2];   // [64, 768]
    const float* W     = (const float*)d_in[3];   // [1, 768]
    const float* b     = (const float*)d_in[4];   // [1]
    const int*   smask = (const int*)d_in[5];     // [64]
    float* out = (float*)d_out;

    small_kernel<<<1, 256>>>(hist, mtl, W, b, smask, out);

    int blocks = (TOTAL_E4 + 255) / 256;          // 6144
    bert_kernel<<<blocks, 256>>>((const float4*)bert, (float4*)out);
}

// round 7
// speedup vs baseline: 2.2144x; 2.2144x over previous
#include <cuda_runtime.h>
#include <cuda_bf16.h>

// Problem constants (fixed shapes)
#define S_NUM   16
#define T_MAX   11
#define ROWS    64
#define HID     768
#define SEQ     512

#define BERT_ELEMS   (S_NUM * SEQ * HID)        // 6291456
#define MTL_OFF      BERT_ELEMS
#define MTL_ELEMS    (S_NUM * HID)              // 12288
#define PROBS_OFF    (MTL_OFF + MTL_ELEMS)

#define H4           (HID / 4)                  // 192 float4 per hidden vector
#define E4_PER_SLICE (SEQ * H4)                 // 98304 float4 per slice
#define TOTAL_E4     (S_NUM * E4_PER_SLICE)     // 1572864
#define HALF_E4      (TOTAL_E4 / 2)             // 786432 (== 8 slices, same e)

#define BERT_BLOCKS  (HALF_E4 / 256)            // 3072
#define MTL_E4       (MTL_ELEMS / 4)            // 3072
#define MTL_BLOCKS   (MTL_E4 / 256)             // 12

// Scratch (no device mallocs allowed)
__device__ int   g_off[S_NUM];
__device__ int   g_ns[S_NUM];
__device__ float g_w[ROWS];

// ---------------------------------------------------------------------------
// Kernel A: offsets, 64 dot-products (1 warp per 2 rows), softmax, weights,
// probs output. One block, 1024 threads.
// ---------------------------------------------------------------------------
__global__ void __launch_bounds__(1024, 1)
small_kernel(const float4* __restrict__ hist,    // [ROWS, H4]
             const float4* __restrict__ W4,      // [H4]
             const float*  __restrict__ b,       // [1]
             const int*    __restrict__ slice_mask,
             float*        __restrict__ out)
{
    __shared__ float s_d[ROWS];          // dot(hist[row], W) + bias
    __shared__ int   s_off[S_NUM];
    __shared__ int   s_ns[S_NUM];
    __shared__ float s_probs[S_NUM * T_MAX];

    const int tid  = threadIdx.x;
    const int lane = tid & 31;
    const int wid  = tid >> 5;           // 0..31

    // 1) offsets (independent of dot products)
    if (tid == 0) {
        int off = 0;
        #pragma unroll
        for (int s = 0; s < S_NUM; s++) {
            int n = slice_mask[s];
            s_off[s] = off; s_ns[s] = n;
            g_off[s] = off; g_ns[s] = n;
            off += n;
        }
    }

    // 2) dot products: warp w handles rows 2w and 2w+1 (float4 vectorized)
    const float bias = b[0];
    {
        float acc0 = 0.f, acc1 = 0.f;
        const float4* h0 = hist + (2 * wid + 0) * H4;
        const float4* h1 = hist + (2 * wid + 1) * H4;
        #pragma unroll
        for (int k = lane; k < H4; k += 32) {
            float4 w = W4[k];
            float4 a = h0[k];
            float4 c = h1[k];
            acc0 += a.x * w.x + a.y * w.y + a.z * w.z + a.w * w.w;
            acc1 += c.x * w.x + c.y * w.y + c.z * w.z + c.w * w.w;
        }
        #pragma unroll
        for (int d = 16; d > 0; d >>= 1) {
            acc0 += __shfl_xor_sync(0xffffffffu, acc0, d);
            acc1 += __shfl_xor_sync(0xffffffffu, acc1, d);
        }
        if (lane == 0) {
            s_d[2 * wid + 0] = acc0 + bias;
            s_d[2 * wid + 1] = acc1 + bias;
        }
    }
    __syncthreads();

    // 3) softmax per slice + per-row weights (16 threads)
    if (tid < S_NUM) {
        int s = tid;
        int n   = s_ns[s];
        int off = s_off[s];
        int pad = T_MAX - n;
        float e[T_MAX];
        float denom = 0.f;
        #pragma unroll
        for (int t = 0; t < T_MAX; t++) {
            float v = (t >= pad) ? expf(s_d[off + t - pad]) : 0.f;
            e[t] = v;
            denom += v;
        }
        float inv = 1.f / denom;
        #pragma unroll
        for (int t = 0; t < T_MAX; t++)
            s_probs[s * T_MAX + t] = e[t] * inv;
        for (int j = 0; j < n; j++)
            g_w[off + j] = e[pad + j] * inv;
    }
    __syncthreads();

    // 4) write probs output
    if (tid < S_NUM * T_MAX)
        out[PROBS_OFF + tid] = s_probs[tid];
}

// ---------------------------------------------------------------------------
// Kernel B: weighted segment-sums.
//  - blocks [0, BERT_BLOCKS): bert, 2 float4 per thread (i and i+HALF_E4,
//    same e, slices s and s+8) -> 8 front-batched LDG.128 per thread.
//  - blocks [BERT_BLOCKS, BERT_BLOCKS+MTL_BLOCKS): mtl segment-sum.
// ---------------------------------------------------------------------------
__global__ void __launch_bounds__(256)
big_kernel(const float4* __restrict__ bert,
           const float4* __restrict__ mtl4,
           float* __restrict__ out)
{
    const int bid = blockIdx.x;
    const int tid = threadIdx.x;

    if (bid < BERT_BLOCKS) {
        int i  = bid * 256 + tid;            // [0, HALF_E4)
        int s1 = i / E4_PER_SLICE;           // 0..7
        int e  = i - s1 * E4_PER_SLICE;
        int s2 = s1 + 8;

        int off1 = g_off[s1], n1 = g_ns[s1];
        int off2 = g_off[s2], n2 = g_ns[s2];

        float4 acc1 = make_float4(0.f, 0.f, 0.f, 0.f);
        float4 acc2 = make_float4(0.f, 0.f, 0.f, 0.f);
        #pragma unroll 4
        for (int j = 0; j < n1; j++) {
            float w  = g_w[off1 + j];
            float4 v = bert[(long)(off1 + j) * E4_PER_SLICE + e];
            acc1.x += w * v.x; acc1.y += w * v.y;
            acc1.z += w * v.z; acc1.w += w * v.w;
        }
        #pragma unroll 4
        for (int j = 0; j < n2; j++) {
            float w  = g_w[off2 + j];
            float4 v = bert[(long)(off2 + j) * E4_PER_SLICE + e];
            acc2.x += w * v.x; acc2.y += w * v.y;
            acc2.z += w * v.z; acc2.w += w * v.w;
        }
        float4* out4 = (float4*)out;
        out4[(long)s1 * E4_PER_SLICE + e] = acc1;
        out4[(long)s2 * E4_PER_SLICE + e] = acc2;
    } else {
        // mtl segment-sum: 3072 float4 outputs
        int i = (bid - BERT_BLOCKS) * 256 + tid;   // [0, MTL_E4)
        int s = i / H4;
        int e = i - s * H4;
        int off = g_off[s], n = g_ns[s];
        float4 acc = make_float4(0.f, 0.f, 0.f, 0.f);
        #pragma unroll 4
        for (int j = 0; j < n; j++) {
            float w  = g_w[off + j];
            float4 v = mtl4[(off + j) * H4 + e];
            acc.x += w * v.x; acc.y += w * v.y;
            acc.z += w * v.z; acc.w += w * v.w;
        }
        float4* out4 = (float4*)(out + MTL_OFF);
        out4[i] = acc;
    }
}

extern "C" void kernel_launch(void* const* d_in, const int* in_sizes, int n_in,
                              void* d_out, int out_size)
{
    const float* bert  = (const float*)d_in[0];   // [64, 512, 768]
    const float* hist  = (const float*)d_in[1];   // [64, 768]
    const float* mtl   = (const float*)d_in[2];   // [64, 768]
    const float* W     = (const float*)d_in[3];   // [1, 768]
    const float* b     = (const float*)d_in[4];   // [1]
    const int*   smask = (const int*)d_in[5];     // [64]
    float* out = (float*)d_out;

    small_kernel<<<1, 1024>>>((const float4*)hist, (const float4*)W, b, smask, out);
    big_kernel<<<BERT_BLOCKS + MTL_BLOCKS, 256>>>((const float4*)bert,
                                                  (const float4*)mtl, out);
}